// round 11
// baseline (speedup 1.0000x reference)
#include <cuda_runtime.h>
#include <cuda_bf16.h>

#define POOL 7
#define NCELL 49
#define C 256
#define SMS 148
#define NBKT 512   // batch(1b) x level(2b) x yq(3b) x xq(3b)
#define MAXBOX 4096

__device__ int g_perm[MAXBOX];

// Single-block bucket sort: groups boxes by (batch, level, quantized center).
__global__ __launch_bounds__(512) void sort_boxes_kernel(
    const float* __restrict__ boxes,
    const float* __restrict__ meta,
    int N, int BN)
{
    __shared__ unsigned short s_key[2048];
    __shared__ int s_cnt[NBKT];
    __shared__ int s_base[NBKT];
    __shared__ int s_cur[NBKT];

    const int tid = threadIdx.x;
    const int n = min(BN, 2048);           // s_key capacity guard

    for (int b = tid; b < NBKT; b += 512) { s_cnt[b] = 0; s_cur[b] = 0; }
    __syncthreads();

    const float area  = meta[4] * meta[5];
    const float denom = 224.0f / sqrtf(area);

    for (int i = tid; i < n; i += 512) {
        const float by1 = boxes[i * 4 + 0];
        const float bx1 = boxes[i * 4 + 1];
        const float by2 = boxes[i * 4 + 2];
        const float bx2 = boxes[i * 4 + 3];

        const float lvl = log2f(sqrtf((by2 - by1) * (bx2 - bx1)) / denom);
        float lv = 4.0f + rintf(lvl);
        lv = fminf(fmaxf(lv, 2.0f), 5.0f);
        const int level = (int)lv;
        const int batch = i / N;

        const float yc = 0.5f * (by1 + by2);
        const float xc = 0.5f * (bx1 + bx2);
        const int yq = min(max((int)(yc * 8.0f), 0), 7);
        const int xq = min(max((int)(xc * 8.0f), 0), 7);

        int key = ((((batch & 1) * 4 + (level - 2)) * 8 + yq) * 8) + xq;
        key &= (NBKT - 1);
        s_key[i] = (unsigned short)key;
        atomicAdd(&s_cnt[key], 1);
    }
    __syncthreads();

    if (tid == 0) {                        // 512-entry serial scan: cheap
        int acc = 0;
        for (int b = 0; b < NBKT; b++) { s_base[b] = acc; acc += s_cnt[b]; }
    }
    __syncthreads();

    for (int i = tid; i < n; i += 512) {
        const int key = s_key[i];
        const int pos = s_base[key] + atomicAdd(&s_cur[key], 1);
        if (pos < MAXBOX) g_perm[pos] = i; // permutation; per-box output unaffected by order
    }
    // identity tail for any boxes beyond the sort capacity
    for (int i = n + tid; i < BN && i < MAXBOX; i += 512) g_perm[i] = i;
}

__global__ __launch_bounds__(256) void roi_align_kernel(
    const float* __restrict__ boxes,
    const float* __restrict__ meta,
    const float* __restrict__ f2,
    const float* __restrict__ f3,
    const float* __restrict__ f4,
    const float* __restrict__ f5,
    float* __restrict__ out,
    int N, int BN, int W)
{
    // Transposed remap: blocks co-resident on one SM (bid == r mod 148) take
    // CONSECUTIVE sorted boxes -> same level + neighborhood -> L1 line reuse.
    const int bid = blockIdx.x;
    const int sorted_idx = (bid % SMS) * W + bid / SMS;
    if (sorted_idx >= BN) return;
    const int box_id = g_perm[sorted_idx];
    const int batch  = box_id / N;
    const int tid    = threadIdx.x;

    __shared__ int4   s_off[NCELL];
    __shared__ float2 s_frac[NCELL];       // {fx, fy}

    const float by1 = boxes[box_id * 4 + 0];
    const float bx1 = boxes[box_id * 4 + 1];
    const float by2 = boxes[box_id * 4 + 2];
    const float bx2 = boxes[box_id * 4 + 3];

    const float area = meta[4] * meta[5];
    const float lvl  = log2f(sqrtf((by2 - by1) * (bx2 - bx1)) / (224.0f / sqrtf(area)));
    float lv = 4.0f + rintf(lvl);          // rintf = round-half-even = jnp.round
    lv = fminf(fmaxf(lv, 2.0f), 5.0f);
    const int level = (int)lv;

    int Hs;
    const float* f;
    if (level == 2)      { Hs = 256; f = f2; }
    else if (level == 3) { Hs = 128; f = f3; }
    else if (level == 4) { Hs = 64;  f = f4; }
    else                 { Hs = 32;  f = f5; }
    const int Ws = Hs;
    const float* base = f + (size_t)batch * Hs * Ws * C;

    if (tid < NCELL) {
        const int py = tid / POOL;
        const int px = tid - py * POOL;

        const float ys = by1 * (float)(Hs - 1)
                       + (float)py * ((by2 - by1) * (float)(Hs - 1) / (float)(POOL - 1));
        const float xs = bx1 * (float)(Ws - 1)
                       + (float)px * ((bx2 - bx1) * (float)(Ws - 1) / (float)(POOL - 1));

        const float y0f = floorf(ys);
        const float x0f = floorf(xs);
        int y0 = min(max((int)y0f, 0), Hs - 1);
        int x0 = min(max((int)x0f, 0), Ws - 1);
        const int y1 = min(y0 + 1, Hs - 1);
        const int x1 = min(x0 + 1, Ws - 1);

        s_off[tid]  = make_int4((y0 * Ws + x0) * C, (y0 * Ws + x1) * C,
                                (y1 * Ws + x0) * C, (y1 * Ws + x1) * C);
        s_frac[tid] = make_float2(xs - x0f, ys - y0f);
    }
    __syncthreads();

    const int ch = (tid & 63) * 4;         // channel offset
    const int g  = tid >> 6;               // cell group 0..3
    const float* bch   = base + ch;
    float*       obase = out + (size_t)box_id * (NCELL * C) + ch;

    auto do_cell = [&](int cell) {
        const int4   off = s_off[cell];
        const float2 fr  = s_frac[cell];

        const float4 tl = *(const float4*)(bch + off.x);   // default .ca: keep L1 hits
        const float4 tr = *(const float4*)(bch + off.y);
        const float4 bl = *(const float4*)(bch + off.z);
        const float4 br = *(const float4*)(bch + off.w);

        float4 o;
        {
            const float top = tl.x + (tr.x - tl.x) * fr.x;
            const float bot = bl.x + (br.x - bl.x) * fr.x;
            o.x = top + (bot - top) * fr.y;
        }
        {
            const float top = tl.y + (tr.y - tl.y) * fr.x;
            const float bot = bl.y + (br.y - bl.y) * fr.x;
            o.y = top + (bot - top) * fr.y;
        }
        {
            const float top = tl.z + (tr.z - tl.z) * fr.x;
            const float bot = bl.z + (br.z - bl.z) * fr.x;
            o.z = top + (bot - top) * fr.y;
        }
        {
            const float top = tl.w + (tr.w - tl.w) * fr.x;
            const float bot = bl.w + (br.w - bl.w) * fr.x;
            o.w = top + (bot - top) * fr.y;
        }
        __stwt((float4*)(obase + (size_t)cell * C), o);    // streaming: keep L2 for reads
    };

    #pragma unroll 1
    for (int k = 0; k < 6; k++) {
        const int c0 = g + 8 * k;
        do_cell(c0);
        do_cell(c0 + 4);
    }
    if (g == 0) do_cell(48);
}

extern "C" void kernel_launch(void* const* d_in, const int* in_sizes, int n_in,
                              void* d_out, int out_size) {
    const float* boxes = (const float*)d_in[0];
    const float* meta  = (const float*)d_in[1];
    const float* f2    = (const float*)d_in[2];
    const float* f3    = (const float*)d_in[3];
    const float* f4    = (const float*)d_in[4];
    const float* f5    = (const float*)d_in[5];
    float* out = (float*)d_out;

    const int BN = in_sizes[0] / 4;                    // total boxes = B*N
    const int B  = in_sizes[2] / (256 * 256 * 256);    // feat2 = B*256*256*C
    const int N  = BN / B;

    sort_boxes_kernel<<<1, 512>>>(boxes, meta, N, BN);

    const int W = (BN + SMS - 1) / SMS;                // sorted boxes per SM column
    roi_align_kernel<<<SMS * W, 256>>>(boxes, meta, f2, f3, f4, f5, out, N, BN, W);
}